// round 8
// baseline (speedup 1.0000x reference)
#include <cuda_runtime.h>
#include <cuda_fp16.h>
#include <cstdint>

#define B_    8
#define CIN   512
#define COUT  512
#define HW    64
#define CKK   4608
#define PLANE 4096
#define EPSV  1e-8f

#define NCHUNK 72            // 8 ci-blocks x 9 kk
#define NT     256           // couts per CTA
#define NTHR   512

// ---- dynamic smem layout (bytes) ----
#define OFF_B    0           // 2 x 32768 (double-buffered B tile: 256 co x 128B)
#define OFF_AH   65536       // A halo tile: 264 hp x 64 ci fp16 = 33792
#define OFF_SLAB 99328       // 64 ci x 265 f32 = 67840
#define OFF_F    167168      // 512 f32
#define OFF_INVD 169216      // 256 f32
#define OFF_BIAS 170240      // 256 f32
#define SMEM_SZ  171264

// ---- device scratch ----
__device__ unsigned short g_w16[(size_t)COUT * CKK];   // fp16 normalized W [co][kk*512+ci]
__device__ float g_q[COUT * CIN];
__device__ float g_f[B_ * CIN];
__device__ float g_invd[B_ * COUT];

__device__ __forceinline__ uint32_t smem_u32(const void* p) {
    uint32_t a;
    asm("{ .reg .u64 t; cvta.to.shared.u64 t, %1; cvt.u32.u64 %0, t; }" : "=r"(a) : "l"(p));
    return a;
}

#define LDSM4(R, addr)                                                          \
    asm volatile("ldmatrix.sync.aligned.m8n8.x4.shared.b16 {%0,%1,%2,%3}, [%4];"\
        : "=r"((R)[0]), "=r"((R)[1]), "=r"((R)[2]), "=r"((R)[3]) : "r"(addr))
#define MMA16816(D, A, B0, B1)                                                  \
    asm volatile("mma.sync.aligned.m16n8k16.row.col.f32.f16.f16.f32 "           \
        "{%0,%1,%2,%3}, {%4,%5,%6,%7}, {%8,%9}, {%0,%1,%2,%3};"                 \
        : "+f"((D)[0]), "+f"((D)[1]), "+f"((D)[2]), "+f"((D)[3])                \
        : "r"((A)[0]), "r"((A)[1]), "r"((A)[2]), "r"((A)[3]), "r"(B0), "r"(B1))
#define CPA16(dst, src)                                                         \
    asm volatile("cp.async.cg.shared.global [%0], [%1], 16;" :: "r"(dst), "l"(src))
#define CPA_COMMIT() asm volatile("cp.async.commit_group;" ::: "memory")
#define CPA_WAIT0()  asm volatile("cp.async.wait_group 0;" ::: "memory")
#define CPA_WAIT1()  asm volatile("cp.async.wait_group 1;" ::: "memory")

// ---------------------------------------------------------------------------
// prep kernels
// ---------------------------------------------------------------------------
__global__ void k_prep_w(const float* __restrict__ weight) {
    const int co = blockIdx.x, tid = threadIdx.x;
    __shared__ float red[256];
    const float* wrow = weight + (size_t)co * CKK;
    float m = 0.0f;
    for (int i = tid; i < CKK; i += 256) m = fmaxf(m, fabsf(wrow[i]));
    red[tid] = m;
    __syncthreads();
    for (int s = 128; s > 0; s >>= 1) {
        if (tid < s) red[tid] = fmaxf(red[tid], red[tid + s]);
        __syncthreads();
    }
    const float inv = (1.0f / sqrtf((float)CKK)) / red[0];
    for (int ci = tid; ci < CIN; ci += 256) {
        float qs = 0.0f;
#pragma unroll
        for (int kk = 0; kk < 9; ++kk) {
            float v = wrow[ci * 9 + kk] * inv;
            g_w16[(size_t)co * CKK + kk * 512 + ci] = __half_as_ushort(__float2half_rn(v));
            qs += v * v;
        }
        g_q[co * CIN + ci] = qs;
    }
}

__global__ void k_prep_s(const float* __restrict__ style) {
    const int b = threadIdx.x >> 5, lane = threadIdx.x & 31;
    float m = 0.0f;
#pragma unroll
    for (int t = 0; t < 16; ++t) m = fmaxf(m, fabsf(style[b * CIN + lane + 32 * t]));
#pragma unroll
    for (int o = 16; o; o >>= 1) m = fmaxf(m, __shfl_xor_sync(~0u, m, o));
    const float inv = (1.0f / sqrtf((float)CKK)) / m;
#pragma unroll
    for (int t = 0; t < 16; ++t) {
        int ci = lane + 32 * t;
        g_f[b * CIN + ci] = style[b * CIN + ci] * inv;
    }
}

__global__ void k_demod() {
    const int co = blockIdx.x;
    const int b = threadIdx.x >> 5, lane = threadIdx.x & 31;
    float s = 0.0f;
#pragma unroll
    for (int t = 0; t < 16; ++t) {
        int ci = lane + 32 * t;
        float f = g_f[b * CIN + ci];
        s += f * f * g_q[co * CIN + ci];
    }
#pragma unroll
    for (int o = 16; o; o >>= 1) s += __shfl_xor_sync(~0u, s, o);
    if (lane == 0) g_invd[b * COUT + co] = rsqrtf(s * (float)CKK + EPSV);
}

// ---------------------------------------------------------------------------
// main conv: fp16 mma.sync implicit GEMM, 16 warps, warp tile 32x64
// ---------------------------------------------------------------------------
__global__ __launch_bounds__(NTHR, 1) void k_conv(
    const float* __restrict__ x,
    const float* __restrict__ noise,
    const float* __restrict__ bias,
    const float* __restrict__ nsp,
    float* __restrict__ out)
{
    extern __shared__ char smem[];
    const uint32_t sb = smem_u32(smem);
    const int tid = threadIdx.x;
    const int wid = tid >> 5, lane = tid & 31;
    const int y0 = blockIdx.x * 2;
    const int coBase = blockIdx.y * NT;
    const int b = blockIdx.z;

    float* slab   = (float*)(smem + OFF_SLAB);
    float* f_s    = (float*)(smem + OFF_F);
    float* invd_s = (float*)(smem + OFF_INVD);
    float* bias_s = (float*)(smem + OFF_BIAS);

    for (int i = tid; i < CIN; i += NTHR) f_s[i] = g_f[b * CIN + i];
    if (tid < NT) {
        invd_s[tid] = g_invd[b * COUT + coBase + tid];
        bias_s[tid] = bias[coBase + tid];
    }

    // ---- issue B tile for chunk 0 ----
    {
        const unsigned short* gsrc = g_w16 + (size_t)coBase * CKK;  // cib=0,kk=0
        const uint32_t Bb = sb + OFF_B;
#pragma unroll
        for (int it = 0; it < 4; ++it) {
            int e = tid + it * NTHR;
            int r = e >> 3, u = e & 7;
            CPA16(Bb + r * 128 + ((u ^ (r & 7)) << 4), gsrc + (size_t)r * CKK + u * 8);
        }
        CPA_COMMIT();
    }

    float acc[64];
#pragma unroll
    for (int i = 0; i < 64; ++i) acc[i] = 0.0f;

    const int wm = wid & 3, wn = wid >> 2;       // warp grid 4(M) x 4(N)
    const int lr = lane & 15, lc = lane >> 4;
    uint32_t bRB[4], kxB[4];
#pragma unroll
    for (int t = 0; t < 4; ++t) {
        bRB[t] = (uint32_t)((wn * 64 + t * 16 + lr) * 128);
        kxB[t] = ((uint32_t)(t * 32 + lc * 16)) ^ ((uint32_t)((lr & 7) << 4));
    }

    for (int c = 0; c < NCHUNK; ++c) {
        const int cib = c / 9;
        const int kk  = c - cib * 9;
        const int dy = kk / 3, dx = kk - dy * 3;

        if (kk == 0) {
            __syncthreads();                     // MMA[c-1] done with A halo + slab
            // ---- refill modulated x slab (fp32, coalesced) ----
            const int cig0 = cib * 64;
            for (int idx = tid; idx < 64 * 264; idx += NTHR) {
                int ci = idx / 264;
                int rem = idx - ci * 264;
                int r = rem / 66, cc = rem - r * 66;
                int gy = y0 - 1 + r, gx = cc - 1;
                float v = 0.0f;
                if ((unsigned)gy < HW && (unsigned)gx < HW)
                    v = x[((size_t)(b * CIN + cig0 + ci) * HW + gy) * HW + gx] * f_s[cig0 + ci];
                slab[ci * 265 + rem] = v;
            }
            __syncthreads();
            // ---- build fp16 A halo tile once: 264 hp x 64 ci, row-swizzled ----
            {
                const int cp = lane;             // ci-pair index
                const int base0 = (2 * cp) * 265;
                const int base1 = base0 + 265;
#pragma unroll
                for (int it = 0; it < 17; ++it) {
                    int hp = wid + it * 16;      // halo pixel 0..263
                    if (hp < 264) {
                        float v0 = slab[base0 + hp];
                        float v1 = slab[base1 + hp];
                        uint32_t h;
                        asm("cvt.rn.f16x2.f32 %0, %1, %2;" : "=r"(h) : "f"(v1), "f"(v0));
                        *(uint32_t*)(smem + OFF_AH + hp * 128 + ((cp * 4) ^ ((hp & 7) << 4))) = h;
                    }
                }
            }
        }

        __syncthreads();                         // prev MMA done / A build done

        // ---- prefetch B[c+1] ----
        if (c + 1 < NCHUNK) {
            const int c1 = c + 1;
            const int cib1 = c1 / 9, kk1 = c1 - cib1 * 9;
            const unsigned short* gsrc = g_w16 + (size_t)coBase * CKK + kk1 * 512 + cib1 * 64;
            const uint32_t Bb = sb + OFF_B + (c1 & 1) * 32768;
#pragma unroll
            for (int it = 0; it < 4; ++it) {
                int e = tid + it * NTHR;
                int r = e >> 3, u = e & 7;
                CPA16(Bb + r * 128 + ((u ^ (r & 7)) << 4), gsrc + (size_t)r * CKK + u * 8);
            }
            CPA_COMMIT();
            CPA_WAIT1();                         // B[c] arrived (B[c+1] in flight)
        } else {
            CPA_WAIT0();
        }
        __syncthreads();                         // B[c] visible to all

        // ---- per-kk shifted A row addresses (warp covers M rows wm*32..+31) ----
        uint32_t aAddr[2], aSw[2];
#pragma unroll
        for (int t = 0; t < 2; ++t) {
            int hp = ((wm >> 1) + dy) * 66 + (wm & 1) * 32 + t * 16 + lr + dx;
            aAddr[t] = sb + OFF_AH + hp * 128;
            aSw[t]   = (uint32_t)((hp & 7) << 4);
        }
        const uint32_t lcx = (uint32_t)(lc << 4);

        // ---- MMA phase: 4 k16 steps ----
        const uint32_t Bb = sb + OFF_B + (c & 1) * 32768;
#pragma unroll
        for (int ks = 0; ks < 4; ++ks) {
            uint32_t af[2][4], bf[4][4];
            const uint32_t ko = (uint32_t)(ks << 5);
#pragma unroll
            for (int t = 0; t < 2; ++t) LDSM4(af[t], aAddr[t] + ((ko | lcx) ^ aSw[t]));
#pragma unroll
            for (int t = 0; t < 4; ++t) LDSM4(bf[t], Bb + bRB[t] + kxB[ks]);
#pragma unroll
            for (int tm = 0; tm < 2; ++tm)
#pragma unroll
                for (int tn = 0; tn < 4; ++tn) {
                    MMA16816(acc + (tm * 8 + tn * 2) * 4,     af[tm], bf[tn][0], bf[tn][2]);
                    MMA16816(acc + (tm * 8 + tn * 2 + 1) * 4, af[tm], bf[tn][1], bf[tn][3]);
                }
        }
    }

    // ---- epilogue ----
    {
        const float nsv = nsp[0];
        const int y = y0 + (wm >> 1);
        const float* nrow = noise + (size_t)b * PLANE + y * HW;
        float* orow = out + ((size_t)(b * COUT + coBase)) * PLANE + y * HW;
#pragma unroll
        for (int tm = 0; tm < 2; ++tm)
#pragma unroll
            for (int h = 0; h < 2; ++h) {
                const int px = (wm & 1) * 32 + tm * 16 + (lane >> 2) + 8 * h;
                const float nz = nrow[px] * nsv;
#pragma unroll
                for (int tn8 = 0; tn8 < 8; ++tn8) {
                    const int co = wn * 64 + tn8 * 8 + (lane & 3) * 2;
                    const float d0 = acc[(tm * 8 + tn8) * 4 + 2 * h];
                    const float d1 = acc[(tm * 8 + tn8) * 4 + 2 * h + 1];
                    orow[(size_t)co * PLANE + px]       = d0 * invd_s[co]     + bias_s[co]     + nz;
                    orow[(size_t)(co + 1) * PLANE + px] = d1 * invd_s[co + 1] + bias_s[co + 1] + nz;
                }
            }
    }
}

// ---------------------------------------------------------------------------
extern "C" void kernel_launch(void* const* d_in, const int* in_sizes, int n_in,
                              void* d_out, int out_size) {
    const float* x      = (const float*)d_in[0];
    const float* style  = (const float*)d_in[1];
    const float* noise  = (const float*)d_in[2];
    const float* weight = (const float*)d_in[3];
    const float* bias   = (const float*)d_in[4];
    const float* nsp    = (const float*)d_in[5];
    float* out          = (float*)d_out;

    k_prep_w<<<COUT, 256>>>(weight);
    k_prep_s<<<1, 256>>>(style);
    k_demod<<<COUT, 256>>>();

    cudaFuncSetAttribute(k_conv, cudaFuncAttributeMaxDynamicSharedMemorySize, SMEM_SZ);
    dim3 grid(32, 2, B_);
    k_conv<<<grid, NTHR, SMEM_SZ>>>(x, noise, bias, nsp, out);
}

// round 10
// speedup vs baseline: 1.3575x; 1.3575x over previous
#include <cuda_runtime.h>
#include <cuda_fp16.h>
#include <cstdint>

#define B_    8
#define CIN   512
#define COUT  512
#define HW    64
#define CKK   4608
#define PLANE 4096
#define EPSV  1e-8f

#define NCHUNK 72            // 8 ci-blocks x 9 kk
#define NT     128           // couts per CTA
#define NTHR   256

// ---- dynamic smem layout (bytes) ----
#define OFF_B    0           // 2 x 16384 (double-buffered B tile: 128 co x 128B)
#define BBUF     16384
#define OFF_AH   32768       // A halo tile: 264 hp x 64 ci fp16 = 33792
#define OFF_SLAB 66560       // 64 ci x 266 fp16 = 34048
#define OFF_F    100608      // 512 f32
#define OFF_INVD 102656      // 128 f32
#define OFF_BIAS 103168      // 128 f32
#define SMEM_SZ  103680

// ---- device scratch ----
__device__ unsigned short g_w16[(size_t)COUT * CKK];   // fp16 normalized W [co][kk*512+ci]
__device__ float g_q[COUT * CIN];
__device__ float g_f[B_ * CIN];
__device__ float g_invd[B_ * COUT];

__device__ __forceinline__ uint32_t smem_u32(const void* p) {
    uint32_t a;
    asm("{ .reg .u64 t; cvta.to.shared.u64 t, %1; cvt.u32.u64 %0, t; }" : "=r"(a) : "l"(p));
    return a;
}

#define LDSM4(R, addr)                                                          \
    asm volatile("ldmatrix.sync.aligned.m8n8.x4.shared.b16 {%0,%1,%2,%3}, [%4];"\
        : "=r"((R)[0]), "=r"((R)[1]), "=r"((R)[2]), "=r"((R)[3]) : "r"(addr))
#define MMA16816(D, A, B0, B1)                                                  \
    asm volatile("mma.sync.aligned.m16n8k16.row.col.f32.f16.f16.f32 "           \
        "{%0,%1,%2,%3}, {%4,%5,%6,%7}, {%8,%9}, {%0,%1,%2,%3};"                 \
        : "+f"((D)[0]), "+f"((D)[1]), "+f"((D)[2]), "+f"((D)[3])                \
        : "r"((A)[0]), "r"((A)[1]), "r"((A)[2]), "r"((A)[3]), "r"(B0), "r"(B1))
#define CPA16(dst, src)                                                         \
    asm volatile("cp.async.cg.shared.global [%0], [%1], 16;" :: "r"(dst), "l"(src))
#define CPA_COMMIT() asm volatile("cp.async.commit_group;" ::: "memory")
#define CPA_WAIT0()  asm volatile("cp.async.wait_group 0;" ::: "memory")
#define CPA_WAIT1()  asm volatile("cp.async.wait_group 1;" ::: "memory")

// ---------------------------------------------------------------------------
// prep kernels
// ---------------------------------------------------------------------------
__global__ void k_prep_w(const float* __restrict__ weight) {
    const int co = blockIdx.x, tid = threadIdx.x;
    __shared__ float red[256];
    const float* wrow = weight + (size_t)co * CKK;
    float m = 0.0f;
    for (int i = tid; i < CKK; i += 256) m = fmaxf(m, fabsf(wrow[i]));
    red[tid] = m;
    __syncthreads();
    for (int s = 128; s > 0; s >>= 1) {
        if (tid < s) red[tid] = fmaxf(red[tid], red[tid + s]);
        __syncthreads();
    }
    const float inv = (1.0f / sqrtf((float)CKK)) / red[0];
    for (int ci = tid; ci < CIN; ci += 256) {
        float qs = 0.0f;
#pragma unroll
        for (int kk = 0; kk < 9; ++kk) {
            float v = wrow[ci * 9 + kk] * inv;
            g_w16[(size_t)co * CKK + kk * 512 + ci] = __half_as_ushort(__float2half_rn(v));
            qs += v * v;
        }
        g_q[co * CIN + ci] = qs;
    }
}

__global__ void k_prep_s(const float* __restrict__ style) {
    const int b = threadIdx.x >> 5, lane = threadIdx.x & 31;
    float m = 0.0f;
#pragma unroll
    for (int t = 0; t < 16; ++t) m = fmaxf(m, fabsf(style[b * CIN + lane + 32 * t]));
#pragma unroll
    for (int o = 16; o; o >>= 1) m = fmaxf(m, __shfl_xor_sync(~0u, m, o));
    const float inv = (1.0f / sqrtf((float)CKK)) / m;
#pragma unroll
    for (int t = 0; t < 16; ++t) {
        int ci = lane + 32 * t;
        g_f[b * CIN + ci] = style[b * CIN + ci] * inv;
    }
}

__global__ void k_demod() {
    const int co = blockIdx.x;
    const int b = threadIdx.x >> 5, lane = threadIdx.x & 31;
    float s = 0.0f;
#pragma unroll
    for (int t = 0; t < 16; ++t) {
        int ci = lane + 32 * t;
        float f = g_f[b * CIN + ci];
        s += f * f * g_q[co * CIN + ci];
    }
#pragma unroll
    for (int o = 16; o; o >>= 1) s += __shfl_xor_sync(~0u, s, o);
    if (lane == 0) g_invd[b * COUT + co] = rsqrtf(s * (float)CKK + EPSV);
}

// ---------------------------------------------------------------------------
// main conv: fp16 mma.sync implicit GEMM, 8 warps, 2 CTAs/SM
// M=128 pixels x N=128 couts x K=4608 per CTA
// ---------------------------------------------------------------------------
__global__ __launch_bounds__(NTHR, 2) void k_conv(
    const float* __restrict__ x,
    const float* __restrict__ noise,
    const float* __restrict__ bias,
    const float* __restrict__ nsp,
    float* __restrict__ out)
{
    extern __shared__ char smem[];
    const uint32_t sb = smem_u32(smem);
    const int tid = threadIdx.x;
    const int wid = tid >> 5, lane = tid & 31;
    const int y0 = blockIdx.x * 2;
    const int coBase = blockIdx.y * NT;
    const int b = blockIdx.z;

    unsigned short* slab16 = (unsigned short*)(smem + OFF_SLAB);
    float* f_s    = (float*)(smem + OFF_F);
    float* invd_s = (float*)(smem + OFF_INVD);
    float* bias_s = (float*)(smem + OFF_BIAS);

    for (int i = tid; i < CIN; i += NTHR) f_s[i] = g_f[b * CIN + i];
    if (tid < NT) {
        invd_s[tid] = g_invd[b * COUT + coBase + tid];
        bias_s[tid] = bias[coBase + tid];
    }

    // ---- issue B tile for chunk 0 ----
    {
        const unsigned short* gsrc = g_w16 + (size_t)coBase * CKK;  // cib=0,kk=0
        const uint32_t Bb = sb + OFF_B;
#pragma unroll
        for (int it = 0; it < 4; ++it) {
            int e = tid + it * NTHR;
            int r = e >> 3, u = e & 7;
            CPA16(Bb + r * 128 + ((u ^ (r & 7)) << 4), gsrc + (size_t)r * CKK + u * 8);
        }
        CPA_COMMIT();
    }

    float acc[64];
#pragma unroll
    for (int i = 0; i < 64; ++i) acc[i] = 0.0f;

    const int wm = wid & 1, wn = wid >> 1;       // warp grid 2(M) x 4(N)
    const int lr = lane & 15, lc = lane >> 4;
    uint32_t bRB[2], kxB[4];
#pragma unroll
    for (int t = 0; t < 2; ++t)
        bRB[t] = (uint32_t)((wn * 32 + t * 16 + lr) * 128);
#pragma unroll
    for (int t = 0; t < 4; ++t)
        kxB[t] = ((uint32_t)(t * 32 + lc * 16)) ^ ((uint32_t)((lr & 7) << 4));

    for (int c = 0; c < NCHUNK; ++c) {
        const int cib = c / 9;
        const int kk  = c - cib * 9;
        const int dy = kk / 3, dx = kk - dy * 3;

        if (kk == 0) {
            __syncthreads();                     // MMA[c-1] done with A halo + slab
            // ---- refill modulated x slab (fp16, 2 pixels/thread, coalesced) ----
            const int cig0 = cib * 64;
            for (int idx = tid; idx < 64 * 132; idx += NTHR) {
                int ci = idx / 132;
                int pr = idx - ci * 132;
                int rem0 = 2 * pr;
                int r = rem0 / 66, cc = rem0 - r * 66;
                int gy = y0 - 1 + r;
                int gx0 = cc - 1, gx1 = cc;
                const float fm = f_s[cig0 + ci];
                float v0 = 0.0f, v1 = 0.0f;
                if ((unsigned)gy < HW) {
                    const float* xr = x + ((size_t)(b * CIN + cig0 + ci) * HW + gy) * HW;
                    if ((unsigned)gx0 < HW) v0 = xr[gx0] * fm;
                    if ((unsigned)gx1 < HW) v1 = xr[gx1] * fm;
                }
                uint32_t h;
                asm("cvt.rn.f16x2.f32 %0, %1, %2;" : "=r"(h) : "f"(v1), "f"(v0));
                *(uint32_t*)(slab16 + ci * 266 + rem0) = h;
            }
            __syncthreads();
            // ---- build fp16 A halo tile once: 264 hp x 64 ci, row-swizzled ----
            {
                const int cp = lane;             // ci-pair index
                const unsigned short* s0 = slab16 + (2 * cp) * 266;
                const unsigned short* s1 = s0 + 266;
#pragma unroll
                for (int it = 0; it < 33; ++it) {
                    int hp = wid + it * 8;       // halo pixel 0..263
                    uint32_t h = (uint32_t)s0[hp] | ((uint32_t)s1[hp] << 16);
                    *(uint32_t*)(smem + OFF_AH + hp * 128 + ((cp * 4) ^ ((hp & 7) << 4))) = h;
                }
            }
        }

        __syncthreads();                         // prev MMA done / A build done

        // ---- prefetch B[c+1] ----
        if (c + 1 < NCHUNK) {
            const int c1 = c + 1;
            const int cib1 = c1 / 9, kk1 = c1 - cib1 * 9;
            const unsigned short* gsrc = g_w16 + (size_t)coBase * CKK + kk1 * 512 + cib1 * 64;
            const uint32_t Bb = sb + OFF_B + (c1 & 1) * BBUF;
#pragma unroll
            for (int it = 0; it < 4; ++it) {
                int e = tid + it * NTHR;
                int r = e >> 3, u = e & 7;
                CPA16(Bb + r * 128 + ((u ^ (r & 7)) << 4), gsrc + (size_t)r * CKK + u * 8);
            }
            CPA_COMMIT();
            CPA_WAIT1();                         // B[c] arrived (B[c+1] in flight)
        } else {
            CPA_WAIT0();
        }
        __syncthreads();                         // B[c] visible to all

        // ---- per-kk shifted A row addresses ----
        uint32_t aAddr[4], aSw[4];
#pragma unroll
        for (int t = 0; t < 4; ++t) {
            int hp = (wm + dy) * 66 + t * 16 + lr + dx;
            aAddr[t] = sb + OFF_AH + hp * 128;
            aSw[t]   = (uint32_t)((hp & 7) << 4);
        }
        const uint32_t lcx = (uint32_t)(lc << 4);

        // ---- MMA phase: 4 k16 steps ----
        const uint32_t Bb = sb + OFF_B + (c & 1) * BBUF;
#pragma unroll
        for (int ks = 0; ks < 4; ++ks) {
            uint32_t af[4][4], bf[2][4];
            const uint32_t ko = (uint32_t)(ks << 5);
#pragma unroll
            for (int t = 0; t < 4; ++t) LDSM4(af[t], aAddr[t] + ((ko | lcx) ^ aSw[t]));
#pragma unroll
            for (int t = 0; t < 2; ++t) LDSM4(bf[t], Bb + bRB[t] + kxB[ks]);
#pragma unroll
            for (int tm = 0; tm < 4; ++tm)
#pragma unroll
                for (int tn = 0; tn < 2; ++tn) {
                    MMA16816(acc + (tm * 4 + tn * 2) * 4,     af[tm], bf[tn][0], bf[tn][2]);
                    MMA16816(acc + (tm * 4 + tn * 2 + 1) * 4, af[tm], bf[tn][1], bf[tn][3]);
                }
        }
    }

    // ---- epilogue ----
    {
        const float nsv = nsp[0];
        const int y = y0 + wm;
        const float* nrow = noise + (size_t)b * PLANE + y * HW;
        float* orow = out + ((size_t)(b * COUT + coBase)) * PLANE + y * HW;
#pragma unroll
        for (int tm = 0; tm < 4; ++tm)
#pragma unroll
            for (int h = 0; h < 2; ++h) {
                const int px = tm * 16 + (lane >> 2) + 8 * h;
                const float nz = nrow[px] * nsv;
#pragma unroll
                for (int tn4 = 0; tn4 < 4; ++tn4) {
                    const int co = wn * 32 + tn4 * 8 + (lane & 3) * 2;
                    const float d0 = acc[(tm * 4 + tn4) * 4 + 2 * h];
                    const float d1 = acc[(tm * 4 + tn4) * 4 + 2 * h + 1];
                    orow[(size_t)co * PLANE + px]       = d0 * invd_s[co]     + bias_s[co]     + nz;
                    orow[(size_t)(co + 1) * PLANE + px] = d1 * invd_s[co + 1] + bias_s[co + 1] + nz;
                }
            }
    }
}

// ---------------------------------------------------------------------------
extern "C" void kernel_launch(void* const* d_in, const int* in_sizes, int n_in,
                              void* d_out, int out_size) {
    const float* x      = (const float*)d_in[0];
    const float* style  = (const float*)d_in[1];
    const float* noise  = (const float*)d_in[2];
    const float* weight = (const float*)d_in[3];
    const float* bias   = (const float*)d_in[4];
    const float* nsp    = (const float*)d_in[5];
    float* out          = (float*)d_out;

    k_prep_w<<<COUT, 256>>>(weight);
    k_prep_s<<<1, 256>>>(style);
    k_demod<<<COUT, 256>>>();

    cudaFuncSetAttribute(k_conv, cudaFuncAttributeMaxDynamicSharedMemorySize, SMEM_SZ);
    dim3 grid(32, COUT / NT, B_);
    k_conv<<<grid, NTHR, SMEM_SZ>>>(x, noise, bias, nsp, out);
}

// round 11
// speedup vs baseline: 1.4917x; 1.0989x over previous
#include <cuda_runtime.h>
#include <cuda_fp16.h>
#include <cstdint>

#define B_    8
#define CIN   512
#define COUT  512
#define HW    64
#define CKK   4608
#define PLANE 4096
#define EPSV  1e-8f

#define NCHUNK 72            // 8 ci-blocks x 9 kk
#define NT     128           // couts per CTA
#define NTHR   256

// ---- dynamic smem layout (bytes) ----
#define OFF_B    0           // 2 x 16384 (double-buffered B tile: 128 co x 128B)
#define BBUF     16384
#define OFF_AH   32768       // 2 x (264 hp x 64 ci fp16 = 33792) double-buffered A halo
#define AHBUF    33792
#define OFF_F    100352      // 512 f32
#define OFF_INVD 102400      // 128 f32
#define OFF_BIAS 102912      // 128 f32
#define SMEM_SZ  103424

// ---- device scratch ----
__device__ unsigned short g_w16[(size_t)COUT * CKK];   // fp16 normalized W [co][kk*512+ci]
__device__ float g_q[COUT * CIN];
__device__ float g_f[B_ * CIN];
__device__ float g_invd[B_ * COUT];

__device__ __forceinline__ uint32_t smem_u32(const void* p) {
    uint32_t a;
    asm("{ .reg .u64 t; cvta.to.shared.u64 t, %1; cvt.u32.u64 %0, t; }" : "=r"(a) : "l"(p));
    return a;
}

#define LDSM4(R, addr)                                                          \
    asm volatile("ldmatrix.sync.aligned.m8n8.x4.shared.b16 {%0,%1,%2,%3}, [%4];"\
        : "=r"((R)[0]), "=r"((R)[1]), "=r"((R)[2]), "=r"((R)[3]) : "r"(addr))
#define MMA16816(D, A, B0, B1)                                                  \
    asm volatile("mma.sync.aligned.m16n8k16.row.col.f32.f16.f16.f32 "           \
        "{%0,%1,%2,%3}, {%4,%5,%6,%7}, {%8,%9}, {%0,%1,%2,%3};"                 \
        : "+f"((D)[0]), "+f"((D)[1]), "+f"((D)[2]), "+f"((D)[3])                \
        : "r"((A)[0]), "r"((A)[1]), "r"((A)[2]), "r"((A)[3]), "r"(B0), "r"(B1))
#define CPA16(dst, src)                                                         \
    asm volatile("cp.async.cg.shared.global [%0], [%1], 16;" :: "r"(dst), "l"(src))
#define CPA_COMMIT() asm volatile("cp.async.commit_group;" ::: "memory")
#define CPA_WAIT0()  asm volatile("cp.async.wait_group 0;" ::: "memory")
#define CPA_WAIT1()  asm volatile("cp.async.wait_group 1;" ::: "memory")

// ---------------------------------------------------------------------------
// prep kernels
// ---------------------------------------------------------------------------
__global__ void k_prep_w(const float* __restrict__ weight) {
    const int co = blockIdx.x, tid = threadIdx.x;
    __shared__ float red[256];
    const float* wrow = weight + (size_t)co * CKK;
    float m = 0.0f;
    for (int i = tid; i < CKK; i += 256) m = fmaxf(m, fabsf(wrow[i]));
    red[tid] = m;
    __syncthreads();
    for (int s = 128; s > 0; s >>= 1) {
        if (tid < s) red[tid] = fmaxf(red[tid], red[tid + s]);
        __syncthreads();
    }
    const float inv = (1.0f / sqrtf((float)CKK)) / red[0];
    for (int ci = tid; ci < CIN; ci += 256) {
        float qs = 0.0f;
#pragma unroll
        for (int kk = 0; kk < 9; ++kk) {
            float v = wrow[ci * 9 + kk] * inv;
            g_w16[(size_t)co * CKK + kk * 512 + ci] = __half_as_ushort(__float2half_rn(v));
            qs += v * v;
        }
        g_q[co * CIN + ci] = qs;
    }
}

__global__ void k_prep_s(const float* __restrict__ style) {
    const int b = threadIdx.x >> 5, lane = threadIdx.x & 31;
    float m = 0.0f;
#pragma unroll
    for (int t = 0; t < 16; ++t) m = fmaxf(m, fabsf(style[b * CIN + lane + 32 * t]));
#pragma unroll
    for (int o = 16; o; o >>= 1) m = fmaxf(m, __shfl_xor_sync(~0u, m, o));
    const float inv = (1.0f / sqrtf((float)CKK)) / m;
#pragma unroll
    for (int t = 0; t < 16; ++t) {
        int ci = lane + 32 * t;
        g_f[b * CIN + ci] = style[b * CIN + ci] * inv;
    }
}

__global__ void k_demod() {
    const int co = blockIdx.x;
    const int b = threadIdx.x >> 5, lane = threadIdx.x & 31;
    float s = 0.0f;
#pragma unroll
    for (int t = 0; t < 16; ++t) {
        int ci = lane + 32 * t;
        float f = g_f[b * CIN + ci];
        s += f * f * g_q[co * CIN + ci];
    }
#pragma unroll
    for (int o = 16; o; o >>= 1) s += __shfl_xor_sync(~0u, s, o);
    if (lane == 0) g_invd[b * COUT + co] = rsqrtf(s * (float)CKK + EPSV);
}

// ---------------------------------------------------------------------------
// A-halo build slice: direct global -> swizzled fp16 SMEM (no slab)
// elements: 64 ci x 264 hp = 16896 = 66 iters x 256 threads
// ---------------------------------------------------------------------------
__device__ __forceinline__ void build_slice(
    char* smem, uint32_t ahOff,
    const float* __restrict__ x, const float* __restrict__ f_s,
    int b, int y0, int cib, int jBeg, int jEnd, int tid)
{
    const int cig0 = cib * 64;
    for (int j = jBeg; j < jEnd; ++j) {
        int idx = j * NTHR + tid;
        int ci = idx / 264;
        int hp = idx - ci * 264;
        int r = hp / 66, cc = hp - r * 66;
        int gy = y0 - 1 + r, gx = cc - 1;
        float v = 0.0f;
        if ((unsigned)gy < HW && (unsigned)gx < HW)
            v = x[((size_t)(b * CIN + cig0 + ci) * HW + gy) * HW + gx] * f_s[cig0 + ci];
        unsigned short hv = __half_as_ushort(__float2half_rn(v));
        *(unsigned short*)(smem + ahOff + hp * 128 +
                           (((unsigned)(ci * 2)) ^ (unsigned)((hp & 7) << 4))) = hv;
    }
}

// ---------------------------------------------------------------------------
// main conv: fp16 mma.sync implicit GEMM, 8 warps, 2 CTAs/SM,
// double-buffered A-halo with build distributed across chunks
// ---------------------------------------------------------------------------
__global__ __launch_bounds__(NTHR, 2) void k_conv(
    const float* __restrict__ x,
    const float* __restrict__ noise,
    const float* __restrict__ bias,
    const float* __restrict__ nsp,
    float* __restrict__ out)
{
    extern __shared__ char smem[];
    const uint32_t sb = smem_u32(smem);
    const int tid = threadIdx.x;
    const int wid = tid >> 5, lane = tid & 31;
    const int y0 = blockIdx.x * 2;
    const int coBase = blockIdx.y * NT;
    const int b = blockIdx.z;

    float* f_s    = (float*)(smem + OFF_F);
    float* invd_s = (float*)(smem + OFF_INVD);
    float* bias_s = (float*)(smem + OFF_BIAS);

    for (int i = tid; i < CIN; i += NTHR) f_s[i] = g_f[b * CIN + i];
    if (tid < NT) {
        invd_s[tid] = g_invd[b * COUT + coBase + tid];
        bias_s[tid] = bias[coBase + tid];
    }

    // ---- issue B tile for chunk 0 (overlaps initial A build) ----
    {
        const unsigned short* gsrc = g_w16 + (size_t)coBase * CKK;  // cib=0,kk=0
        const uint32_t Bb = sb + OFF_B;
#pragma unroll
        for (int it = 0; it < 4; ++it) {
            int e = tid + it * NTHR;
            int r = e >> 3, u = e & 7;
            CPA16(Bb + r * 128 + ((u ^ (r & 7)) << 4), gsrc + (size_t)r * CKK + u * 8);
        }
        CPA_COMMIT();
    }

    __syncthreads();                              // f_s ready for build
    // ---- full initial A-halo build for cib=0 into AH buffer 0 ----
    build_slice(smem, OFF_AH, x, f_s, b, y0, 0, 0, 66, tid);

    float acc[64];
#pragma unroll
    for (int i = 0; i < 64; ++i) acc[i] = 0.0f;

    const int wm = wid & 1, wn = wid >> 1;       // warp grid 2(M) x 4(N)
    const int lr = lane & 15, lc = lane >> 4;
    uint32_t bRB[2], kxB[4];
#pragma unroll
    for (int t = 0; t < 2; ++t)
        bRB[t] = (uint32_t)((wn * 32 + t * 16 + lr) * 128);
#pragma unroll
    for (int t = 0; t < 4; ++t)
        kxB[t] = ((uint32_t)(t * 32 + lc * 16)) ^ ((uint32_t)((lr & 7) << 4));

    for (int c = 0; c < NCHUNK; ++c) {
        const int cib = c / 9;
        const int kk  = c - cib * 9;
        const int dy = kk / 3, dx = kk - dy * 3;
        const uint32_t ahCur = OFF_AH + (uint32_t)(cib & 1) * AHBUF;

        __syncthreads();                         // MMA[c-1] done (B buf free; at block
                                                 // boundary: AH[next] writes complete)

        // ---- prefetch B[c+1] ----
        if (c + 1 < NCHUNK) {
            const int c1 = c + 1;
            const int cib1 = c1 / 9, kk1 = c1 - cib1 * 9;
            const unsigned short* gsrc = g_w16 + (size_t)coBase * CKK + kk1 * 512 + cib1 * 64;
            const uint32_t Bb = sb + OFF_B + (c1 & 1) * BBUF;
#pragma unroll
            for (int it = 0; it < 4; ++it) {
                int e = tid + it * NTHR;
                int r = e >> 3, u = e & 7;
                CPA16(Bb + r * 128 + ((u ^ (r & 7)) << 4), gsrc + (size_t)r * CKK + u * 8);
            }
            CPA_COMMIT();
        }

        // ---- distributed A-halo build slice for next ci-block ----
        if (cib < 7) {
            const int jBeg = kk * 8;
            const int jEnd = (kk == 8) ? 66 : (jBeg + 8);
            build_slice(smem, OFF_AH + (uint32_t)((cib + 1) & 1) * AHBUF,
                        x, f_s, b, y0, cib + 1, jBeg, jEnd, tid);
        }

        if (c + 1 < NCHUNK) CPA_WAIT1();         // B[c] arrived (B[c+1] in flight)
        else                CPA_WAIT0();
        __syncthreads();                         // B[c] visible to all

        // ---- per-kk shifted A row addresses ----
        uint32_t aAddr[4], aSw[4];
#pragma unroll
        for (int t = 0; t < 4; ++t) {
            int hp = (wm + dy) * 66 + t * 16 + lr + dx;
            aAddr[t] = sb + ahCur + hp * 128;
            aSw[t]   = (uint32_t)((hp & 7) << 4);
        }
        const uint32_t lcx = (uint32_t)(lc << 4);

        // ---- MMA phase: 4 k16 steps ----
        const uint32_t Bb = sb + OFF_B + (c & 1) * BBUF;
#pragma unroll
        for (int ks = 0; ks < 4; ++ks) {
            uint32_t af[4][4], bf[2][4];
            const uint32_t ko = (uint32_t)(ks << 5);
#pragma unroll
            for (int t = 0; t < 4; ++t) LDSM4(af[t], aAddr[t] + ((ko | lcx) ^ aSw[t]));
#pragma unroll
            for (int t = 0; t < 2; ++t) LDSM4(bf[t], Bb + bRB[t] + kxB[ks]);
#pragma unroll
            for (int tm = 0; tm < 4; ++tm)
#pragma unroll
                for (int tn = 0; tn < 2; ++tn) {
                    MMA16816(acc + (tm * 4 + tn * 2) * 4,     af[tm], bf[tn][0], bf[tn][2]);
                    MMA16816(acc + (tm * 4 + tn * 2 + 1) * 4, af[tm], bf[tn][1], bf[tn][3]);
                }
        }
    }

    // ---- epilogue ----
    {
        const float nsv = nsp[0];
        const int y = y0 + wm;
        const float* nrow = noise + (size_t)b * PLANE + y * HW;
        float* orow = out + ((size_t)(b * COUT + coBase)) * PLANE + y * HW;
#pragma unroll
        for (int tm = 0; tm < 4; ++tm)
#pragma unroll
            for (int h = 0; h < 2; ++h) {
                const int px = tm * 16 + (lane >> 2) + 8 * h;
                const float nz = nrow[px] * nsv;
#pragma unroll
                for (int tn4 = 0; tn4 < 4; ++tn4) {
                    const int co = wn * 32 + tn4 * 8 + (lane & 3) * 2;
                    const float d0 = acc[(tm * 4 + tn4) * 4 + 2 * h];
                    const float d1 = acc[(tm * 4 + tn4) * 4 + 2 * h + 1];
                    orow[(size_t)co * PLANE + px]       = d0 * invd_s[co]     + bias_s[co]     + nz;
                    orow[(size_t)(co + 1) * PLANE + px] = d1 * invd_s[co + 1] + bias_s[co + 1] + nz;
                }
            }
    }
}

// ---------------------------------------------------------------------------
extern "C" void kernel_launch(void* const* d_in, const int* in_sizes, int n_in,
                              void* d_out, int out_size) {
    const float* x      = (const float*)d_in[0];
    const float* style  = (const float*)d_in[1];
    const float* noise  = (const float*)d_in[2];
    const float* weight = (const float*)d_in[3];
    const float* bias   = (const float*)d_in[4];
    const float* nsp    = (const float*)d_in[5];
    float* out          = (float*)d_out;

    k_prep_w<<<COUT, 256>>>(weight);
    k_prep_s<<<1, 256>>>(style);
    k_demod<<<COUT, 256>>>();

    cudaFuncSetAttribute(k_conv, cudaFuncAttributeMaxDynamicSharedMemorySize, SMEM_SZ);
    dim3 grid(32, COUT / NT, B_);
    k_conv<<<grid, NTHR, SMEM_SZ>>>(x, noise, bias, nsp, out);
}

// round 12
// speedup vs baseline: 2.2573x; 1.5132x over previous
#include <cuda_runtime.h>
#include <cuda_fp16.h>
#include <cstdint>

#define B_    8
#define CIN   512
#define COUT  512
#define HW    64
#define CKK   4608
#define PLANE 4096
#define EPSV  1e-8f

#define NCHUNK 72            // 8 ci-blocks x 9 kk
#define NT     128           // couts per CTA
#define NTHR   256

// ---- dynamic smem layout (bytes) ----
#define OFF_B    0           // 2 x 16384 (double-buffered B tile: 128 co x 128B)
#define BBUF     16384
#define OFF_AH   32768       // 2 x (264 hp x 64 ci fp16 = 33792) double-buffered A halo
#define AHBUF    33792
#define OFF_INVD 100352      // 128 f32
#define OFF_BIAS 100864      // 128 f32
#define SMEM_SZ  101376

// ---- device scratch ----
__device__ unsigned short g_w16[(size_t)COUT * CKK];   // fp16 normalized W [co][kk*512+ci]
__device__ unsigned short g_xt[(size_t)B_ * PLANE * CIN]; // fp16 modulated x, pixel-major [b][y][x][ci]
__device__ float g_q[COUT * CIN];
__device__ float g_f[B_ * CIN];
__device__ float g_invd[B_ * COUT];

__device__ __forceinline__ uint32_t smem_u32(const void* p) {
    uint32_t a;
    asm("{ .reg .u64 t; cvta.to.shared.u64 t, %1; cvt.u32.u64 %0, t; }" : "=r"(a) : "l"(p));
    return a;
}

#define LDSM4(R, addr)                                                          \
    asm volatile("ldmatrix.sync.aligned.m8n8.x4.shared.b16 {%0,%1,%2,%3}, [%4];"\
        : "=r"((R)[0]), "=r"((R)[1]), "=r"((R)[2]), "=r"((R)[3]) : "r"(addr))
#define MMA16816(D, A, B0, B1)                                                  \
    asm volatile("mma.sync.aligned.m16n8k16.row.col.f32.f16.f16.f32 "           \
        "{%0,%1,%2,%3}, {%4,%5,%6,%7}, {%8,%9}, {%0,%1,%2,%3};"                 \
        : "+f"((D)[0]), "+f"((D)[1]), "+f"((D)[2]), "+f"((D)[3])                \
        : "r"((A)[0]), "r"((A)[1]), "r"((A)[2]), "r"((A)[3]), "r"(B0), "r"(B1))
#define CPA16(dst, src)                                                         \
    asm volatile("cp.async.cg.shared.global [%0], [%1], 16;" :: "r"(dst), "l"(src))
#define CPA16Z(dst, src, sz)                                                    \
    asm volatile("cp.async.cg.shared.global [%0], [%1], 16, %2;" :: "r"(dst), "l"(src), "r"(sz))
#define CPA_COMMIT() asm volatile("cp.async.commit_group;" ::: "memory")
#define CPA_WAIT0()  asm volatile("cp.async.wait_group 0;" ::: "memory")
#define CPA_WAIT1()  asm volatile("cp.async.wait_group 1;" ::: "memory")

// ---------------------------------------------------------------------------
// prep kernels
// ---------------------------------------------------------------------------
__global__ void k_prep_w(const float* __restrict__ weight) {
    const int co = blockIdx.x, tid = threadIdx.x;
    __shared__ float red[256];
    const float* wrow = weight + (size_t)co * CKK;
    float m = 0.0f;
    for (int i = tid; i < CKK; i += 256) m = fmaxf(m, fabsf(wrow[i]));
    red[tid] = m;
    __syncthreads();
    for (int s = 128; s > 0; s >>= 1) {
        if (tid < s) red[tid] = fmaxf(red[tid], red[tid + s]);
        __syncthreads();
    }
    const float inv = (1.0f / sqrtf((float)CKK)) / red[0];
    for (int ci = tid; ci < CIN; ci += 256) {
        float qs = 0.0f;
#pragma unroll
        for (int kk = 0; kk < 9; ++kk) {
            float v = wrow[ci * 9 + kk] * inv;
            g_w16[(size_t)co * CKK + kk * 512 + ci] = __half_as_ushort(__float2half_rn(v));
            qs += v * v;
        }
        g_q[co * CIN + ci] = qs;
    }
}

__global__ void k_prep_s(const float* __restrict__ style) {
    const int b = threadIdx.x >> 5, lane = threadIdx.x & 31;
    float m = 0.0f;
#pragma unroll
    for (int t = 0; t < 16; ++t) m = fmaxf(m, fabsf(style[b * CIN + lane + 32 * t]));
#pragma unroll
    for (int o = 16; o; o >>= 1) m = fmaxf(m, __shfl_xor_sync(~0u, m, o));
    const float inv = (1.0f / sqrtf((float)CKK)) / m;
#pragma unroll
    for (int t = 0; t < 16; ++t) {
        int ci = lane + 32 * t;
        g_f[b * CIN + ci] = style[b * CIN + ci] * inv;
    }
}

__global__ void k_demod() {
    const int co = blockIdx.x;
    const int b = threadIdx.x >> 5, lane = threadIdx.x & 31;
    float s = 0.0f;
#pragma unroll
    for (int t = 0; t < 16; ++t) {
        int ci = lane + 32 * t;
        float f = g_f[b * CIN + ci];
        s += f * f * g_q[co * CIN + ci];
    }
#pragma unroll
    for (int o = 16; o; o >>= 1) s += __shfl_xor_sync(~0u, s, o);
    if (lane == 0) g_invd[b * COUT + co] = rsqrtf(s * (float)CKK + EPSV);
}

// transpose + modulate: g_xt[b][y][x][ci] = fp16( x[b][ci][y][x] * f[b][ci] )
// grid (64 y, 8 cib, 8 b), block 256
__global__ void k_xpose(const float* __restrict__ x) {
    __shared__ float ts[64][65];
    const int tid = threadIdx.x;
    const int y = blockIdx.x, cib = blockIdx.y, b = blockIdx.z;
    const int cig0 = cib * 64;
    for (int idx = tid; idx < 4096; idx += 256) {
        int ci = idx >> 6, xx = idx & 63;
        ts[ci][xx] = x[((size_t)(b * CIN + cig0 + ci) * HW + y) * HW + xx]
                   * g_f[b * CIN + cig0 + ci];
    }
    __syncthreads();
    uint32_t* dst = (uint32_t*)g_xt;
    for (int idx = tid; idx < 2048; idx += 256) {
        int xx = idx >> 5, cp = idx & 31;
        float v0 = ts[2 * cp][xx], v1 = ts[2 * cp + 1][xx];
        uint32_t h;
        asm("cvt.rn.f16x2.f32 %0, %1, %2;" : "=r"(h) : "f"(v1), "f"(v0));
        dst[(((size_t)b * PLANE + y * HW + xx) * CIN + cig0) / 2 + cp] = h;
    }
}

// ---------------------------------------------------------------------------
// main conv: fp16 mma.sync implicit GEMM, 8 warps, 2 CTAs/SM,
// A-halo built by cp.async from pixel-major g_xt (zero-fill OOB rows)
// ---------------------------------------------------------------------------
__global__ __launch_bounds__(NTHR, 2) void k_conv(
    const float* __restrict__ noise,
    const float* __restrict__ bias,
    const float* __restrict__ nsp,
    float* __restrict__ out)
{
    extern __shared__ char smem[];
    const uint32_t sb = smem_u32(smem);
    const int tid = threadIdx.x;
    const int wid = tid >> 5, lane = tid & 31;
    const int y0 = blockIdx.x * 2;
    const int coBase = blockIdx.y * NT;
    const int b = blockIdx.z;

    float* invd_s = (float*)(smem + OFF_INVD);
    float* bias_s = (float*)(smem + OFF_BIAS);
    if (tid < NT) {
        invd_s[tid] = g_invd[b * COUT + coBase + tid];
        bias_s[tid] = bias[coBase + tid];
    }

    // ---- group 0: B tile for chunk 0 ----
    {
        const unsigned short* gsrc = g_w16 + (size_t)coBase * CKK;  // cib=0,kk=0
        const uint32_t Bb = sb + OFF_B;
#pragma unroll
        for (int it = 0; it < 4; ++it) {
            int e = tid + it * NTHR;
            int r = e >> 3, u = e & 7;
            CPA16(Bb + r * 128 + ((u ^ (r & 7)) << 4), gsrc + (size_t)r * CKK + u * 8);
        }
        CPA_COMMIT();
    }
    // ---- group 1: full A-halo for cib=0 (264 rows x 8 chunks of 16B) ----
    {
#pragma unroll
        for (int it = 0; it < 9; ++it) {
            int e = tid + it * NTHR;
            if (e < 2112) {
                int row = e >> 3, u = e & 7;
                int r = row / 66, cc = row - r * 66;
                int gy = y0 - 1 + r, gx = cc - 1;
                uint32_t ok = ((unsigned)gy < HW && (unsigned)gx < HW) ? 16u : 0u;
                int py = ok ? gy : 0, pxx = ok ? gx : 0;
                const char* src = (const char*)(g_xt + ((size_t)b * PLANE + py * HW + pxx) * CIN) + (u << 4);
                uint32_t dst = sb + OFF_AH + row * 128 + ((u << 4) ^ ((row & 7) << 4));
                CPA16Z(dst, src, ok);
            }
        }
        CPA_COMMIT();
    }

    float acc[64];
#pragma unroll
    for (int i = 0; i < 64; ++i) acc[i] = 0.0f;

    const int wm = wid & 1, wn = wid >> 1;       // warp grid 2(M) x 4(N)
    const int lr = lane & 15, lc = lane >> 4;
    uint32_t bRB[2], kxB[4];
#pragma unroll
    for (int t = 0; t < 2; ++t)
        bRB[t] = (uint32_t)((wn * 32 + t * 16 + lr) * 128);
#pragma unroll
    for (int t = 0; t < 4; ++t)
        kxB[t] = ((uint32_t)(t * 32 + lc * 16)) ^ ((uint32_t)((lr & 7) << 4));

    for (int c = 0; c < NCHUNK; ++c) {
        const int cib = c / 9;
        const int kk  = c - cib * 9;
        const int dy = kk / 3, dx = kk - dy * 3;
        const uint32_t ahCur = OFF_AH + (uint32_t)(cib & 1) * AHBUF;

        __syncthreads();                         // MMA[c-1] done (bufs free)

        // ---- one commit group: B[c+1] + A-slice for block cib+1 ----
        if (c + 1 < NCHUNK) {
            const int c1 = c + 1;
            const int cib1 = c1 / 9, kk1 = c1 - cib1 * 9;
            const unsigned short* gsrc = g_w16 + (size_t)coBase * CKK + kk1 * 512 + cib1 * 64;
            const uint32_t Bb = sb + OFF_B + (c1 & 1) * BBUF;
#pragma unroll
            for (int it = 0; it < 4; ++it) {
                int e = tid + it * NTHR;
                int r = e >> 3, u = e & 7;
                CPA16(Bb + r * 128 + ((u ^ (r & 7)) << 4), gsrc + (size_t)r * CKK + u * 8);
            }
        }
        if (cib < 7) {                           // A rows [kk*30, kk*30+nr) of next block
            const int rBeg = kk * 30;
            const int nr = (kk == 8) ? 24 : 30;
            const int e = tid;
            if (e < nr * 8) {
                int row = rBeg + (e >> 3), u = e & 7;
                int r = row / 66, cc = row - r * 66;
                int gy = y0 - 1 + r, gx = cc - 1;
                uint32_t ok = ((unsigned)gy < HW && (unsigned)gx < HW) ? 16u : 0u;
                int py = ok ? gy : 0, pxx = ok ? gx : 0;
                const char* src = (const char*)(g_xt +
                    ((size_t)b * PLANE + py * HW + pxx) * CIN + (cib + 1) * 64) + (u << 4);
                uint32_t dst = sb + OFF_AH + (uint32_t)((cib + 1) & 1) * AHBUF
                             + row * 128 + ((u << 4) ^ ((row & 7) << 4));
                CPA16Z(dst, src, ok);
            }
        }
        CPA_COMMIT();

        if (c + 1 < NCHUNK) CPA_WAIT1();         // everything up to B[c]/A[cur] done
        else                CPA_WAIT0();
        __syncthreads();                         // visible to all

        // ---- per-kk shifted A row addresses ----
        uint32_t aAddr[4], aSw[4];
#pragma unroll
        for (int t = 0; t < 4; ++t) {
            int hp = (wm + dy) * 66 + t * 16 + lr + dx;
            aAddr[t] = sb + ahCur + hp * 128;
            aSw[t]   = (uint32_t)((hp & 7) << 4);
        }
        const uint32_t lcx = (uint32_t)(lc << 4);

        // ---- MMA phase: 4 k16 steps ----
        const uint32_t Bb = sb + OFF_B + (c & 1) * BBUF;
#pragma unroll
        for (int ks = 0; ks < 4; ++ks) {
            uint32_t af[4][4], bf[2][4];
            const uint32_t ko = (uint32_t)(ks << 5);
#pragma unroll
            for (int t = 0; t < 4; ++t) LDSM4(af[t], aAddr[t] + ((ko | lcx) ^ aSw[t]));
#pragma unroll
            for (int t = 0; t < 2; ++t) LDSM4(bf[t], Bb + bRB[t] + kxB[ks]);
#pragma unroll
            for (int tm = 0; tm < 4; ++tm)
#pragma unroll
                for (int tn = 0; tn < 2; ++tn) {
                    MMA16816(acc + (tm * 4 + tn * 2) * 4,     af[tm], bf[tn][0], bf[tn][2]);
                    MMA16816(acc + (tm * 4 + tn * 2 + 1) * 4, af[tm], bf[tn][1], bf[tn][3]);
                }
        }
    }

    // ---- epilogue ----
    {
        const float nsv = nsp[0];
        const int y = y0 + wm;
        const float* nrow = noise + (size_t)b * PLANE + y * HW;
        float* orow = out + ((size_t)(b * COUT + coBase)) * PLANE + y * HW;
#pragma unroll
        for (int tm = 0; tm < 4; ++tm)
#pragma unroll
            for (int h = 0; h < 2; ++h) {
                const int px = tm * 16 + (lane >> 2) + 8 * h;
                const float nz = nrow[px] * nsv;
#pragma unroll
                for (int tn4 = 0; tn4 < 4; ++tn4) {
                    const int co = wn * 32 + tn4 * 8 + (lane & 3) * 2;
                    const float d0 = acc[(tm * 4 + tn4) * 4 + 2 * h];
                    const float d1 = acc[(tm * 4 + tn4) * 4 + 2 * h + 1];
                    orow[(size_t)co * PLANE + px]       = d0 * invd_s[co]     + bias_s[co]     + nz;
                    orow[(size_t)(co + 1) * PLANE + px] = d1 * invd_s[co + 1] + bias_s[co + 1] + nz;
                }
            }
    }
}

// ---------------------------------------------------------------------------
extern "C" void kernel_launch(void* const* d_in, const int* in_sizes, int n_in,
                              void* d_out, int out_size) {
    const float* x      = (const float*)d_in[0];
    const float* style  = (const float*)d_in[1];
    const float* noise  = (const float*)d_in[2];
    const float* weight = (const float*)d_in[3];
    const float* bias   = (const float*)d_in[4];
    const float* nsp    = (const float*)d_in[5];
    float* out          = (float*)d_out;

    k_prep_w<<<COUT, 256>>>(weight);
    k_prep_s<<<1, 256>>>(style);
    k_demod<<<COUT, 256>>>();
    {
        dim3 g(64, 8, B_);
        k_xpose<<<g, 256>>>(x);
    }

    cudaFuncSetAttribute(k_conv, cudaFuncAttributeMaxDynamicSharedMemorySize, SMEM_SZ);
    dim3 grid(32, COUT / NT, B_);
    k_conv<<<grid, NTHR, SMEM_SZ>>>(noise, bias, nsp, out);
}